// round 12
// baseline (speedup 1.0000x reference)
#include <cuda_runtime.h>
#include <cuda_bf16.h>
#include <cstdint>

#define NN 50000
#define EMAX 600000
#define STRIDE 64

// ---------------- scratch (no allocations allowed) ----------------
__device__ int      g_mode64 = 1;
__device__ int      g_cnt[NN];
__device__ int      g_colidx[NN * STRIDE];
__device__ float    g_uv[NN * 256];   // dual layers: [u(128)|v(128)]; layer2: 128-wide rows
__device__ float    g_alpha[2][128];
__device__ float    g_beta[2][128];
// fragment-ordered split weights (R10-verified layout):
// per layer: ntile(=N/128) x [kt(8) x 2048], kt-block = [hc(2)][nt(16)][j(2)][lane(32)]
__device__ uint32_t g_Bf[81920];      // L0:[0,32768) L1:[32768,65536) L2:[65536,81920)
// bf16 hi/lo split activations for h (written by aggepi; plane 0 = hi, 1 = lo)
__device__ __nv_bfloat16 g_hbf[2][NN * 128];

// ---------------- graph build ----------------
__device__ __forceinline__ int load_idx(const void* ei, long long pos) {
    if (g_mode64) return (int)((const long long*)ei)[pos];
    return ((const int*)ei)[pos];
}

__global__ void k_detect_zero(const long long* __restrict__ ei, long long n) {
    long long i = blockIdx.x * (long long)blockDim.x + threadIdx.x;
    bool bad = false;
    for (; i < n; i += (long long)gridDim.x * blockDim.x) {
        if (i < NN) g_cnt[i] = 0;
        long long v = ei[i];
        bad |= (v < 0) | (v >= NN);
    }
    if (bad) g_mode64 = 0;
}

__global__ void k_fill(const void* ei, long long E) {
    long long e = blockIdx.x * (long long)blockDim.x + threadIdx.x;
    for (; e < E; e += (long long)gridDim.x * blockDim.x) {
        int d = load_idx(ei, E + e);
        int s = load_idx(ei, e);
        int p = atomicAdd(&g_cnt[d], 1);
        if (p < STRIDE) g_colidx[d * STRIDE + p] = s;
    }
}

// ---------------- split helpers ----------------
__device__ __forceinline__ uint32_t pack2(__nv_bfloat16 a, __nv_bfloat16 b) {
    __nv_bfloat162 t; t.x = a; t.y = b;
    return *(uint32_t*)&t;
}

__device__ __forceinline__ void split4(float4 v, uint2& hv, uint2& lv) {
    __nv_bfloat16 hx = __float2bfloat16(v.x);
    __nv_bfloat16 hy = __float2bfloat16(v.y);
    __nv_bfloat16 hz = __float2bfloat16(v.z);
    __nv_bfloat16 hw = __float2bfloat16(v.w);
    hv.x = pack2(hx, hy); hv.y = pack2(hz, hw);
    lv.x = pack2(__float2bfloat16(v.x - __bfloat162float(hx)),
                 __float2bfloat16(v.y - __bfloat162float(hy)));
    lv.y = pack2(__float2bfloat16(v.z - __bfloat162float(hz)),
                 __float2bfloat16(v.w - __bfloat162float(hw)));
}

// ---------------- weight prep (BN fold + fragment-ordered split) --
__device__ __forceinline__ uint32_t pack_split(float w0, float w1, int hc) {
    __nv_bfloat16 h0 = __float2bfloat16(w0);
    __nv_bfloat16 h1 = __float2bfloat16(w1);
    if (hc) {
        h0 = __float2bfloat16(w0 - __bfloat162float(h0));
        h1 = __float2bfloat16(w1 - __bfloat162float(h1));
    }
    return pack2(h0, h1);
}

__global__ void k_prepw(const float* b0, const float* g0, const float* be0,
                        const float* m0, const float* v0,
                        const float* b1, const float* g1, const float* be1,
                        const float* m1, const float* v1,
                        const float* wl0, const float* wr0,
                        const float* wl1, const float* wr1,
                        const float* wl2, const float* wr2) {
    int i = blockIdx.x * blockDim.x + threadIdx.x;
    if (i < 128) {
        float s0 = g0[i] * rsqrtf(v0[i] + 1e-5f);
        g_alpha[0][i] = s0;
        g_beta[0][i]  = (b0[i] - m0[i]) * s0 + be0[i];
        float s1 = g1[i] * rsqrtf(v1[i] + 1e-5f);
        g_alpha[1][i] = s1;
        g_beta[1][i]  = (b1[i] - m1[i]) * s1 + be1[i];
    }
    if (i >= 81920) return;
    int layer, idx;
    if (i < 32768)      { layer = 0; idx = i; }
    else if (i < 65536) { layer = 1; idx = i - 32768; }
    else                { layer = 2; idx = i - 65536; }
    int ntile = idx >> 14;
    int sub   = idx & 16383;
    int kt    = sub >> 11;
    int rem   = sub & 2047;
    int hc    = rem >> 10;
    int rem2  = rem & 1023;
    int nt    = rem2 >> 6;
    int j     = (rem2 >> 5) & 1;
    int lane  = rem2 & 31;
    int g = lane >> 2, tg = lane & 3;
    int k = kt * 16 + j * 8 + tg * 2;
    int n = ntile * 128 + nt * 8 + g;
    float w0, w1;
    if (layer == 2) {
        if (n < 64) { w0 = wl2[k * 64 + n];      w1 = wl2[(k + 1) * 64 + n]; }
        else        { w0 = wr2[k * 64 + n - 64]; w1 = wr2[(k + 1) * 64 + n - 64]; }
    } else {
        const float* wl = layer ? wl1 : wl0;
        const float* wr = layer ? wr1 : wr0;
        if (n < 128) { w0 = wl[k * 128 + n];       w1 = wl[(k + 1) * 128 + n]; }
        else         { w0 = wr[k * 128 + n - 128]; w1 = wr[(k + 1) * 128 + n - 128]; }
    }
    g_Bf[i] = pack_split(w0, w1, hc);
}

// ---------------- tensor-core GEMM (R10 config: M64 tiles, 3 CTA/SM) ---
__device__ __forceinline__ void mma_bf16(float* c, const uint32_t* a, const uint32_t* b) {
    asm volatile(
        "mma.sync.aligned.m16n8k16.row.col.f32.bf16.bf16.f32 "
        "{%0,%1,%2,%3}, {%4,%5,%6,%7}, {%8,%9}, {%0,%1,%2,%3};\n"
        : "+f"(c[0]), "+f"(c[1]), "+f"(c[2]), "+f"(c[3])
        : "r"(a[0]), "r"(a[1]), "r"(a[2]), "r"(a[3]), "r"(b[0]), "r"(b[1]));
}

__device__ __forceinline__ void ldm_x4(uint32_t* r, const void* p) {
    uint32_t addr = (uint32_t)__cvta_generic_to_shared(p);
    asm volatile("ldmatrix.sync.aligned.m8n8.x4.shared.b16 {%0,%1,%2,%3}, [%4];"
                 : "=r"(r[0]), "=r"(r[1]), "=r"(r[2]), "=r"(r[3]) : "r"(addr));
}

__device__ __forceinline__ void cp_async16(uint32_t d, const void* g) {
    asm volatile("cp.async.cg.shared.global [%0], [%1], 16;" :: "r"(d), "l"(g));
}

// smem: A-hi [8 kb][64 rows][32B, swizzled] 16KB, A-lo 16KB, B 2x16KB = 64KB
#define SMA_HI 0
#define SMA_LO 16384
#define SMB    32768
#define SM_TOT 65536

// C[64 rows at blockIdx.x*64, 128 cols at blockIdx.y*128].
// SELA=0: A = fp32 xf, converted inline. SELA=1: A = g_hbf planes via cp.async.
template <int SELA>
__global__ __launch_bounds__(256, 3) void k_gemm7(
    const float* __restrict__ xf, int bfo, float* __restrict__ C, int ldC)
{
    extern __shared__ char sm[];
    uint32_t smb = (uint32_t)__cvta_generic_to_shared(sm);
    uint32_t* sB32 = (uint32_t*)(sm + SMB);

    int tid = threadIdx.x, lane = tid & 31, wid = tid >> 5;
    int warpM = wid & 3, warpN = wid >> 2;      // 4 x 2 warps, tile 16x64 each
    int m0 = blockIdx.x * 64;
    const uint32_t* Bf = g_Bf + bfo + blockIdx.y * 16384;

    float acc[8][4];
    #pragma unroll
    for (int b = 0; b < 8; b++)
        #pragma unroll
        for (int c = 0; c < 4; c++) acc[b][c] = 0.f;

    // ---- stage A (64 rows, full K, hi/lo planes, XOR-swizzled) ----
    if (SELA == 0) {
        #pragma unroll
        for (int q = 0; q < 8; q++) {
            int f = tid + q * 256;               // 0..2047 float4s
            int row = f >> 5, c4 = f & 31;       // row 0..63, k4 0..31
            int gr = m0 + row;
            if (gr >= NN) gr = NN - 1;
            float4 v = ((const float4*)xf)[(long long)gr * 32 + c4];
            uint2 hv, lv;
            split4(v, hv, lv);
            int kb  = c4 >> 2;                   // 16-k block
            int c16 = (c4 >> 1) & 1;             // 16B chunk within kb
            int ph  = c16 ^ ((row >> 2) & 1);
            uint32_t doff = (uint32_t)(kb * 2048 + row * 32 + ph * 16 + (c4 & 1) * 8);
            *(uint2*)(sm + SMA_HI + doff) = hv;
            *(uint2*)(sm + SMA_LO + doff) = lv;
        }
    } else {
        #pragma unroll
        for (int i = 0; i < 4; i++) {
            int idx = tid + i * 256;             // 0..1023 16B-chunks
            int row = idx >> 4, c = idx & 15;
            int kb = c >> 1, ph = (c & 1) ^ ((row >> 2) & 1);
            uint32_t doff = (uint32_t)(kb * 2048 + row * 32 + ph * 16);
            int gr = m0 + row;
            if (gr >= NN) gr = NN - 1;
            long long goff = (long long)gr * 128 + c * 8;
            cp_async16(smb + SMA_HI + doff, g_hbf[0] + goff);
            cp_async16(smb + SMA_LO + doff, g_hbf[1] + goff);
        }
    }
    // B chunk 0 into buf 0
    {
        const uint4* src = (const uint4*)(Bf);
        #pragma unroll
        for (int r = 0; r < 4; r++)
            cp_async16(smb + SMB + tid * 16 + r * 4096, src + tid + r * 256);
    }
    asm volatile("cp.async.commit_group;");          // G0 = (A?) + B0
    {
        const uint4* src = (const uint4*)(Bf + 4096);
        #pragma unroll
        for (int r = 0; r < 4; r++)
            cp_async16(smb + SMB + 16384 + tid * 16 + r * 4096, src + tid + r * 256);
    }
    asm volatile("cp.async.commit_group;");          // G1 = B1

    for (int it = 0; it < 4; it++) {
        if (it < 3) asm volatile("cp.async.wait_group 1;");
        else        asm volatile("cp.async.wait_group 0;");
        __syncthreads();

        int buf = it & 1;
        #pragma unroll
        for (int kt2 = 0; kt2 < 2; kt2++) {
            int kt = it * 2 + kt2;
            uint32_t ah[4], al[4];
            {
                int r = warpM * 16 + (lane & 15);
                int ch = lane >> 4;
                uint32_t off = (uint32_t)(kt * 2048 + r * 32 + ((ch ^ ((r >> 2) & 1)) << 4));
                ldm_x4(ah, sm + SMA_HI + off);
                ldm_x4(al, sm + SMA_LO + off);
            }
            uint32_t bbase = (uint32_t)(buf * 4096 + kt2 * 2048);
            #pragma unroll
            for (int ntl = 0; ntl < 8; ntl++) {
                int nt = warpN * 8 + ntl;
                uint32_t bh[2], bl[2];
                bh[0] = sB32[bbase + nt * 64 + lane];
                bh[1] = sB32[bbase + nt * 64 + 32 + lane];
                bl[0] = sB32[bbase + 1024 + nt * 64 + lane];
                bl[1] = sB32[bbase + 1024 + nt * 64 + 32 + lane];
                mma_bf16(acc[ntl], ah, bh);
                mma_bf16(acc[ntl], ah, bl);
                mma_bf16(acc[ntl], al, bh);
            }
        }
        if (it < 2) {
            __syncthreads();                          // all warps done with buf
            const uint4* src = (const uint4*)(Bf + (it + 2) * 4096);
            uint32_t dst = smb + SMB + (uint32_t)(buf * 16384);
            #pragma unroll
            for (int r = 0; r < 4; r++)
                cp_async16(dst + tid * 16 + r * 4096, src + tid + r * 256);
            asm volatile("cp.async.commit_group;");
        }
    }

    // ---- epilogue: raw fp32 store of fragments ----
    int g = lane >> 2, tg = lane & 3;
    #pragma unroll
    for (int ntl = 0; ntl < 8; ntl++) {
        int c = blockIdx.y * 128 + warpN * 64 + ntl * 8 + tg * 2;
        int r0 = m0 + warpM * 16 + g;
        int r1 = r0 + 8;
        float2 v0 = make_float2(acc[ntl][0], acc[ntl][1]);
        float2 v1 = make_float2(acc[ntl][2], acc[ntl][3]);
        if (r0 < NN) *(float2*)&C[(long long)r0 * ldC + c] = v0;
        if (r1 < NN) *(float2*)&C[(long long)r1 * ldC + c] = v1;
    }
}

// ---------------- fused aggregate + BN/ReLU + bf16-split epilogue ----
// 8 independent gather streams + int4 index loads (MLP 8).
__global__ void k_aggepi(int layer) {
    int warp = (blockIdx.x * blockDim.x + threadIdx.x) >> 5;
    int lane = threadIdx.x & 31;
    if (warp >= NN) return;
    int cnt = g_cnt[warp];
    int end = cnt < STRIDE ? cnt : STRIDE;
    float inv = (cnt > 0) ? 1.0f / (float)cnt : 1.0f;
    const int* bucket = &g_colidx[warp * STRIDE];
    const float4* U4 = (const float4*)g_uv;
    float4 acc[8];
    #pragma unroll
    for (int s = 0; s < 8; s++) acc[s] = make_float4(0.f, 0.f, 0.f, 0.f);
    int j = 0;
    for (; j + 7 < end; j += 8) {
        int4 i0 = *(const int4*)&bucket[j];
        int4 i1 = *(const int4*)&bucket[j + 4];
        float4 u0 = U4[(long long)i0.x * 64 + lane];
        float4 u1 = U4[(long long)i0.y * 64 + lane];
        float4 u2 = U4[(long long)i0.z * 64 + lane];
        float4 u3 = U4[(long long)i0.w * 64 + lane];
        float4 u4 = U4[(long long)i1.x * 64 + lane];
        float4 u5 = U4[(long long)i1.y * 64 + lane];
        float4 u6 = U4[(long long)i1.z * 64 + lane];
        float4 u7 = U4[(long long)i1.w * 64 + lane];
        acc[0].x += u0.x; acc[0].y += u0.y; acc[0].z += u0.z; acc[0].w += u0.w;
        acc[1].x += u1.x; acc[1].y += u1.y; acc[1].z += u1.z; acc[1].w += u1.w;
        acc[2].x += u2.x; acc[2].y += u2.y; acc[2].z += u2.z; acc[2].w += u2.w;
        acc[3].x += u3.x; acc[3].y += u3.y; acc[3].z += u3.z; acc[3].w += u3.w;
        acc[4].x += u4.x; acc[4].y += u4.y; acc[4].z += u4.z; acc[4].w += u4.w;
        acc[5].x += u5.x; acc[5].y += u5.y; acc[5].z += u5.z; acc[5].w += u5.w;
        acc[6].x += u6.x; acc[6].y += u6.y; acc[6].z += u6.z; acc[6].w += u6.w;
        acc[7].x += u7.x; acc[7].y += u7.y; acc[7].z += u7.z; acc[7].w += u7.w;
    }
    if (j + 3 < end) {
        int4 i0 = *(const int4*)&bucket[j];
        float4 u0 = U4[(long long)i0.x * 64 + lane];
        float4 u1 = U4[(long long)i0.y * 64 + lane];
        float4 u2 = U4[(long long)i0.z * 64 + lane];
        float4 u3 = U4[(long long)i0.w * 64 + lane];
        acc[0].x += u0.x; acc[0].y += u0.y; acc[0].z += u0.z; acc[0].w += u0.w;
        acc[1].x += u1.x; acc[1].y += u1.y; acc[1].z += u1.z; acc[1].w += u1.w;
        acc[2].x += u2.x; acc[2].y += u2.y; acc[2].z += u2.z; acc[2].w += u2.w;
        acc[3].x += u3.x; acc[3].y += u3.y; acc[3].z += u3.z; acc[3].w += u3.w;
        j += 4;
    }
    for (; j < end; j++) {
        int s0 = bucket[j];
        float4 u = U4[(long long)s0 * 64 + lane];
        acc[0].x += u.x; acc[0].y += u.y; acc[0].z += u.z; acc[0].w += u.w;
    }
    float4 t;
    t.x = ((acc[0].x + acc[1].x) + (acc[2].x + acc[3].x)) + ((acc[4].x + acc[5].x) + (acc[6].x + acc[7].x));
    t.y = ((acc[0].y + acc[1].y) + (acc[2].y + acc[3].y)) + ((acc[4].y + acc[5].y) + (acc[6].y + acc[7].y));
    t.z = ((acc[0].z + acc[1].z) + (acc[2].z + acc[3].z)) + ((acc[4].z + acc[5].z) + (acc[6].z + acc[7].z));
    t.w = ((acc[0].w + acc[1].w) + (acc[2].w + acc[3].w)) + ((acc[4].w + acc[5].w) + (acc[6].w + acc[7].w));
    float4 v = U4[(long long)warp * 64 + 32 + lane];
    int c = lane * 4;
    const float* al = g_alpha[layer];
    const float* be = g_beta[layer];
    float4 o;
    o.x = fmaxf(fmaf(t.x * inv + v.x, al[c + 0], be[c + 0]), 0.f);
    o.y = fmaxf(fmaf(t.y * inv + v.y, al[c + 1], be[c + 1]), 0.f);
    o.z = fmaxf(fmaf(t.z * inv + v.z, al[c + 2], be[c + 2]), 0.f);
    o.w = fmaxf(fmaf(t.w * inv + v.w, al[c + 3], be[c + 3]), 0.f);
    // write bf16 hi/lo planes (next GEMM input)
    uint2 hv, lv;
    split4(o, hv, lv);
    *(uint2*)&g_hbf[0][(long long)warp * 128 + c] = hv;
    *(uint2*)&g_hbf[1][(long long)warp * 128 + c] = lv;
}

// final: out[i,:] = mean_nbr u2[s] + v2[i] + b2, g_uv rows are 128 floats here
__global__ void k_aggfinal(const float* __restrict__ b2, float* __restrict__ out) {
    int warp = (blockIdx.x * blockDim.x + threadIdx.x) >> 5;
    int lane = threadIdx.x & 31;
    if (warp >= NN) return;
    int cnt = g_cnt[warp];
    int end = cnt < STRIDE ? cnt : STRIDE;
    float inv = (cnt > 0) ? 1.0f / (float)cnt : 1.0f;
    const int* bucket = &g_colidx[warp * STRIDE];
    const float2* U2 = (const float2*)g_uv;
    float2 acc[8];
    #pragma unroll
    for (int s = 0; s < 8; s++) acc[s] = make_float2(0.f, 0.f);
    int j = 0;
    for (; j + 7 < end; j += 8) {
        int4 i0 = *(const int4*)&bucket[j];
        int4 i1 = *(const int4*)&bucket[j + 4];
        float2 u0 = U2[(long long)i0.x * 64 + lane];
        float2 u1 = U2[(long long)i0.y * 64 + lane];
        float2 u2 = U2[(long long)i0.z * 64 + lane];
        float2 u3 = U2[(long long)i0.w * 64 + lane];
        float2 u4 = U2[(long long)i1.x * 64 + lane];
        float2 u5 = U2[(long long)i1.y * 64 + lane];
        float2 u6 = U2[(long long)i1.z * 64 + lane];
        float2 u7 = U2[(long long)i1.w * 64 + lane];
        acc[0].x += u0.x; acc[0].y += u0.y;
        acc[1].x += u1.x; acc[1].y += u1.y;
        acc[2].x += u2.x; acc[2].y += u2.y;
        acc[3].x += u3.x; acc[3].y += u3.y;
        acc[4].x += u4.x; acc[4].y += u4.y;
        acc[5].x += u5.x; acc[5].y += u5.y;
        acc[6].x += u6.x; acc[6].y += u6.y;
        acc[7].x += u7.x; acc[7].y += u7.y;
    }
    if (j + 3 < end) {
        int4 i0 = *(const int4*)&bucket[j];
        float2 u0 = U2[(long long)i0.x * 64 + lane];
        float2 u1 = U2[(long long)i0.y * 64 + lane];
        float2 u2 = U2[(long long)i0.z * 64 + lane];
        float2 u3 = U2[(long long)i0.w * 64 + lane];
        acc[0].x += u0.x; acc[0].y += u0.y;
        acc[1].x += u1.x; acc[1].y += u1.y;
        acc[2].x += u2.x; acc[2].y += u2.y;
        acc[3].x += u3.x; acc[3].y += u3.y;
        j += 4;
    }
    for (; j < end; j++) {
        int s0 = bucket[j];
        float2 u = U2[(long long)s0 * 64 + lane];
        acc[0].x += u.x; acc[0].y += u.y;
    }
    float2 t;
    t.x = ((acc[0].x + acc[1].x) + (acc[2].x + acc[3].x)) + ((acc[4].x + acc[5].x) + (acc[6].x + acc[7].x));
    t.y = ((acc[0].y + acc[1].y) + (acc[2].y + acc[3].y)) + ((acc[4].y + acc[5].y) + (acc[6].y + acc[7].y));
    float2 v  = U2[(long long)warp * 64 + 32 + lane];
    float2 bb = ((const float2*)b2)[lane];
    float2 o;
    o.x = t.x * inv + v.x + bb.x;
    o.y = t.y * inv + v.y + bb.y;
    ((float2*)out)[(long long)warp * 32 + lane] = o;
}

extern "C" void kernel_launch(void* const* d_in, const int* in_sizes, int n_in,
                              void* d_out, int out_size) {
    const float* x    = (const float*)d_in[0];
    const void*  ei   = d_in[1];
    const float* b_l2 = (const float*)d_in[17];

    long long E = in_sizes[1] / 2;
    if (E > EMAX) E = EMAX;

    cudaFuncSetAttribute(k_gemm7<0>, cudaFuncAttributeMaxDynamicSharedMemorySize, SM_TOT);
    cudaFuncSetAttribute(k_gemm7<1>, cudaFuncAttributeMaxDynamicSharedMemorySize, SM_TOT);

    int mBlocks = (NN + 63) / 64;             // 782
    int aBlocks = (NN * 32 + 255) / 256;      // 6250
    float* uv;
    cudaGetSymbolAddress((void**)&uv, g_uv);

    k_detect_zero<<<512, 256>>>((const long long*)ei, E);
    k_fill<<<512, 256>>>(ei, E);
    k_prepw<<<320, 256>>>((const float*)d_in[3], (const float*)d_in[5], (const float*)d_in[6],
                          (const float*)d_in[7], (const float*)d_in[8],
                          (const float*)d_in[10], (const float*)d_in[12], (const float*)d_in[13],
                          (const float*)d_in[14], (const float*)d_in[15],
                          (const float*)d_in[2], (const float*)d_in[4],
                          (const float*)d_in[9], (const float*)d_in[11],
                          (const float*)d_in[16], (const float*)d_in[18]);

    // layer 0: uv = x @ [W_l0 | W_r0]; h = relu(bn0(agg(u)+v)) (split to bf16)
    k_gemm7<0><<<dim3(mBlocks, 2), 256, SM_TOT>>>(x, 0, uv, 256);
    k_aggepi<<<aBlocks, 256>>>(0);
    // layer 1
    k_gemm7<1><<<dim3(mBlocks, 2), 256, SM_TOT>>>(nullptr, 32768, uv, 256);
    k_aggepi<<<aBlocks, 256>>>(1);
    // layer 2 (N=128: u2|v2), then final aggregate
    k_gemm7<1><<<dim3(mBlocks, 1), 256, SM_TOT>>>(nullptr, 65536, uv, 128);
    k_aggfinal<<<aBlocks, 256>>>(b_l2, (float*)d_out);
}

// round 13
// speedup vs baseline: 1.1393x; 1.1393x over previous
#include <cuda_runtime.h>
#include <cuda_bf16.h>
#include <cstdint>

#define NN 50000
#define EMAX 600000
#define STRIDE 64

// ---------------- scratch (no allocations allowed) ----------------
__device__ int      g_mode64 = 1;
__device__ int      g_cnt[NN];
__device__ int      g_colidx[NN * STRIDE];
__device__ float    g_uv[NN * 256];   // dual layers: [u(128)|v(128)]; layer2: 128-wide rows
__device__ float    g_alpha[2][128];
__device__ float    g_beta[2][128];
// fragment-ordered split weights:
// per layer: ntile(=N/128) x [kt(8) x 2048], kt-block = [hc(2)][nt(16)][j(2)][lane(32)]
__device__ uint32_t g_Bf[81920];      // L0:[0,32768) L1:[32768,65536) L2:[65536,81920)
// bf16 hi/lo split activations for h (written by aggepi; plane 0 = hi, 1 = lo)
__device__ __nv_bfloat16 g_hbf[2][NN * 128];

// ---------------- index helpers ----------------
__device__ __forceinline__ int load_idx(const void* ei, long long pos) {
    if (g_mode64) return (int)((const long long*)ei)[pos];
    return ((const int*)ei)[pos];
}

// ---------------- split helpers ----------------
__device__ __forceinline__ uint32_t pack2(__nv_bfloat16 a, __nv_bfloat16 b) {
    __nv_bfloat162 t; t.x = a; t.y = b;
    return *(uint32_t*)&t;
}

__device__ __forceinline__ void split4(float4 v, uint2& hv, uint2& lv) {
    __nv_bfloat16 hx = __float2bfloat16(v.x);
    __nv_bfloat16 hy = __float2bfloat16(v.y);
    __nv_bfloat16 hz = __float2bfloat16(v.z);
    __nv_bfloat16 hw = __float2bfloat16(v.w);
    hv.x = pack2(hx, hy); hv.y = pack2(hz, hw);
    lv.x = pack2(__float2bfloat16(v.x - __bfloat162float(hx)),
                 __float2bfloat16(v.y - __bfloat162float(hy)));
    lv.y = pack2(__float2bfloat16(v.z - __bfloat162float(hz)),
                 __float2bfloat16(v.w - __bfloat162float(hw)));
}

__device__ __forceinline__ uint32_t pack_split(float w0, float w1, int hc) {
    __nv_bfloat16 h0 = __float2bfloat16(w0);
    __nv_bfloat16 h1 = __float2bfloat16(w1);
    if (hc) {
        h0 = __float2bfloat16(w0 - __bfloat162float(h0));
        h1 = __float2bfloat16(w1 - __bfloat162float(h1));
    }
    return pack2(h0, h1);
}

// ---------------- fused prolog: zero counters + width-detect + weight prep ----
// Detection scans only the first 2048 int64 words: if the buffer is really
// int32 pairs, a word looks "valid" only if its high int32 is 0 (P ~ 2e-5),
// so 2048 words misdetect with probability ~0.
__global__ void k_pre(const long long* __restrict__ ei, long long nwords,
                      const float* b0, const float* g0, const float* be0,
                      const float* m0, const float* v0,
                      const float* b1, const float* g1, const float* be1,
                      const float* m1, const float* v1,
                      const float* wl0, const float* wr0,
                      const float* wl1, const float* wr1,
                      const float* wl2, const float* wr2) {
    int i = blockIdx.x * blockDim.x + threadIdx.x;
    for (int z = i; z < NN; z += gridDim.x * blockDim.x) g_cnt[z] = 0;
    if (i < 2048 && (long long)i < nwords) {
        long long v = ei[i];
        if (v < 0 || v >= NN) g_mode64 = 0;
    }
    if (i < 128) {
        float s0 = g0[i] * rsqrtf(v0[i] + 1e-5f);
        g_alpha[0][i] = s0;
        g_beta[0][i]  = (b0[i] - m0[i]) * s0 + be0[i];
        float s1 = g1[i] * rsqrtf(v1[i] + 1e-5f);
        g_alpha[1][i] = s1;
        g_beta[1][i]  = (b1[i] - m1[i]) * s1 + be1[i];
    }
    if (i >= 81920) return;
    int layer, idx;
    if (i < 32768)      { layer = 0; idx = i; }
    else if (i < 65536) { layer = 1; idx = i - 32768; }
    else                { layer = 2; idx = i - 65536; }
    int ntile = idx >> 14;
    int sub   = idx & 16383;
    int kt    = sub >> 11;
    int rem   = sub & 2047;
    int hc    = rem >> 10;
    int rem2  = rem & 1023;
    int nt    = rem2 >> 6;
    int j     = (rem2 >> 5) & 1;
    int lane  = rem2 & 31;
    int g = lane >> 2, tg = lane & 3;
    int k = kt * 16 + j * 8 + tg * 2;
    int n = ntile * 128 + nt * 8 + g;
    float w0, w1;
    if (layer == 2) {
        if (n < 64) { w0 = wl2[k * 64 + n];      w1 = wl2[(k + 1) * 64 + n]; }
        else        { w0 = wr2[k * 64 + n - 64]; w1 = wr2[(k + 1) * 64 + n - 64]; }
    } else {
        const float* wl = layer ? wl1 : wl0;
        const float* wr = layer ? wr1 : wr0;
        if (n < 128) { w0 = wl[k * 128 + n];       w1 = wl[(k + 1) * 128 + n]; }
        else         { w0 = wr[k * 128 + n - 128]; w1 = wr[(k + 1) * 128 + n - 128]; }
    }
    g_Bf[i] = pack_split(w0, w1, hc);
}

__global__ void k_fill(const void* ei, long long E) {
    long long e = blockIdx.x * (long long)blockDim.x + threadIdx.x;
    for (; e < E; e += (long long)gridDim.x * blockDim.x) {
        int d = load_idx(ei, E + e);
        int s = load_idx(ei, e);
        int p = atomicAdd(&g_cnt[d], 1);
        if (p < STRIDE) g_colidx[d * STRIDE + p] = s;
    }
}

// ---------------- tensor-core GEMM (R10 config: M64 tiles, 3 CTA/SM) ---
__device__ __forceinline__ void mma_bf16(float* c, const uint32_t* a, const uint32_t* b) {
    asm volatile(
        "mma.sync.aligned.m16n8k16.row.col.f32.bf16.bf16.f32 "
        "{%0,%1,%2,%3}, {%4,%5,%6,%7}, {%8,%9}, {%0,%1,%2,%3};\n"
        : "+f"(c[0]), "+f"(c[1]), "+f"(c[2]), "+f"(c[3])
        : "r"(a[0]), "r"(a[1]), "r"(a[2]), "r"(a[3]), "r"(b[0]), "r"(b[1]));
}

__device__ __forceinline__ void ldm_x4(uint32_t* r, const void* p) {
    uint32_t addr = (uint32_t)__cvta_generic_to_shared(p);
    asm volatile("ldmatrix.sync.aligned.m8n8.x4.shared.b16 {%0,%1,%2,%3}, [%4];"
                 : "=r"(r[0]), "=r"(r[1]), "=r"(r[2]), "=r"(r[3]) : "r"(addr));
}

__device__ __forceinline__ void cp_async16(uint32_t d, const void* g) {
    asm volatile("cp.async.cg.shared.global [%0], [%1], 16;" :: "r"(d), "l"(g));
}

// smem: A-hi [8 kb][64 rows][32B, swizzled] 16KB, A-lo 16KB, B 2x16KB = 64KB
#define SMA_HI 0
#define SMA_LO 16384
#define SMB    32768
#define SM_TOT 65536

// C[64 rows at blockIdx.x*64, 128 cols at blockIdx.y*128].
// SELA=0: A = fp32 xf, converted inline. SELA=1: A = g_hbf planes via cp.async.
template <int SELA>
__global__ __launch_bounds__(256, 3) void k_gemm7(
    const float* __restrict__ xf, int bfo, float* __restrict__ C, int ldC)
{
    extern __shared__ char sm[];
    uint32_t smb = (uint32_t)__cvta_generic_to_shared(sm);
    uint32_t* sB32 = (uint32_t*)(sm + SMB);

    int tid = threadIdx.x, lane = tid & 31, wid = tid >> 5;
    int warpM = wid & 3, warpN = wid >> 2;      // 4 x 2 warps, tile 16x64 each
    int m0 = blockIdx.x * 64;
    const uint32_t* Bf = g_Bf + bfo + blockIdx.y * 16384;

    float acc[8][4];
    #pragma unroll
    for (int b = 0; b < 8; b++)
        #pragma unroll
        for (int c = 0; c < 4; c++) acc[b][c] = 0.f;

    // ---- stage A (64 rows, full K, hi/lo planes, XOR-swizzled) ----
    if (SELA == 0) {
        #pragma unroll
        for (int q = 0; q < 8; q++) {
            int f = tid + q * 256;               // 0..2047 float4s
            int row = f >> 5, c4 = f & 31;       // row 0..63, k4 0..31
            int gr = m0 + row;
            if (gr >= NN) gr = NN - 1;
            float4 v = ((const float4*)xf)[(long long)gr * 32 + c4];
            uint2 hv, lv;
            split4(v, hv, lv);
            int kb  = c4 >> 2;                   // 16-k block
            int c16 = (c4 >> 1) & 1;             // 16B chunk within kb
            int ph  = c16 ^ ((row >> 2) & 1);
            uint32_t doff = (uint32_t)(kb * 2048 + row * 32 + ph * 16 + (c4 & 1) * 8);
            *(uint2*)(sm + SMA_HI + doff) = hv;
            *(uint2*)(sm + SMA_LO + doff) = lv;
        }
    } else {
        #pragma unroll
        for (int i = 0; i < 4; i++) {
            int idx = tid + i * 256;             // 0..1023 16B-chunks
            int row = idx >> 4, c = idx & 15;
            int kb = c >> 1, ph = (c & 1) ^ ((row >> 2) & 1);
            uint32_t doff = (uint32_t)(kb * 2048 + row * 32 + ph * 16);
            int gr = m0 + row;
            if (gr >= NN) gr = NN - 1;
            long long goff = (long long)gr * 128 + c * 8;
            cp_async16(smb + SMA_HI + doff, g_hbf[0] + goff);
            cp_async16(smb + SMA_LO + doff, g_hbf[1] + goff);
        }
    }
    // B chunk 0 into buf 0
    {
        const uint4* src = (const uint4*)(Bf);
        #pragma unroll
        for (int r = 0; r < 4; r++)
            cp_async16(smb + SMB + tid * 16 + r * 4096, src + tid + r * 256);
    }
    asm volatile("cp.async.commit_group;");          // G0 = (A?) + B0
    {
        const uint4* src = (const uint4*)(Bf + 4096);
        #pragma unroll
        for (int r = 0; r < 4; r++)
            cp_async16(smb + SMB + 16384 + tid * 16 + r * 4096, src + tid + r * 256);
    }
    asm volatile("cp.async.commit_group;");          // G1 = B1

    for (int it = 0; it < 4; it++) {
        if (it < 3) asm volatile("cp.async.wait_group 1;");
        else        asm volatile("cp.async.wait_group 0;");
        __syncthreads();

        int buf = it & 1;
        #pragma unroll
        for (int kt2 = 0; kt2 < 2; kt2++) {
            int kt = it * 2 + kt2;
            uint32_t ah[4], al[4];
            {
                int r = warpM * 16 + (lane & 15);
                int ch = lane >> 4;
                uint32_t off = (uint32_t)(kt * 2048 + r * 32 + ((ch ^ ((r >> 2) & 1)) << 4));
                ldm_x4(ah, sm + SMA_HI + off);
                ldm_x4(al, sm + SMA_LO + off);
            }
            uint32_t bbase = (uint32_t)(buf * 4096 + kt2 * 2048);
            #pragma unroll
            for (int ntl = 0; ntl < 8; ntl++) {
                int nt = warpN * 8 + ntl;
                uint32_t bh[2], bl[2];
                bh[0] = sB32[bbase + nt * 64 + lane];
                bh[1] = sB32[bbase + nt * 64 + 32 + lane];
                bl[0] = sB32[bbase + 1024 + nt * 64 + lane];
                bl[1] = sB32[bbase + 1024 + nt * 64 + 32 + lane];
                mma_bf16(acc[ntl], ah, bh);
                mma_bf16(acc[ntl], ah, bl);
                mma_bf16(acc[ntl], al, bh);
            }
        }
        if (it < 2) {
            __syncthreads();                          // all warps done with buf
            const uint4* src = (const uint4*)(Bf + (it + 2) * 4096);
            uint32_t dst = smb + SMB + (uint32_t)(buf * 16384);
            #pragma unroll
            for (int r = 0; r < 4; r++)
                cp_async16(dst + tid * 16 + r * 4096, src + tid + r * 256);
            asm volatile("cp.async.commit_group;");
        }
    }

    // ---- epilogue: raw fp32 store of fragments ----
    int g = lane >> 2, tg = lane & 3;
    #pragma unroll
    for (int ntl = 0; ntl < 8; ntl++) {
        int c = blockIdx.y * 128 + warpN * 64 + ntl * 8 + tg * 2;
        int r0 = m0 + warpM * 16 + g;
        int r1 = r0 + 8;
        float2 v0 = make_float2(acc[ntl][0], acc[ntl][1]);
        float2 v1 = make_float2(acc[ntl][2], acc[ntl][3]);
        if (r0 < NN) *(float2*)&C[(long long)r0 * ldC + c] = v0;
        if (r1 < NN) *(float2*)&C[(long long)r1 * ldC + c] = v1;
    }
}

// ---------------- fused aggregate + BN/ReLU + bf16-split epilogue ----
// (R10-proven 4-stream form)
__global__ void k_aggepi(int layer) {
    int warp = (blockIdx.x * blockDim.x + threadIdx.x) >> 5;
    int lane = threadIdx.x & 31;
    if (warp >= NN) return;
    int cnt = g_cnt[warp];
    int end = cnt < STRIDE ? cnt : STRIDE;
    float inv = (cnt > 0) ? 1.0f / (float)cnt : 1.0f;
    const int* bucket = &g_colidx[warp * STRIDE];
    const float4* U4 = (const float4*)g_uv;
    float4 a0 = make_float4(0.f, 0.f, 0.f, 0.f);
    float4 a1 = make_float4(0.f, 0.f, 0.f, 0.f);
    float4 a2 = make_float4(0.f, 0.f, 0.f, 0.f);
    float4 a3 = make_float4(0.f, 0.f, 0.f, 0.f);
    int j = 0;
    for (; j + 3 < end; j += 4) {
        int s0 = bucket[j], s1 = bucket[j + 1], s2 = bucket[j + 2], s3 = bucket[j + 3];
        float4 u0 = U4[(long long)s0 * 64 + lane];
        float4 u1 = U4[(long long)s1 * 64 + lane];
        float4 u2 = U4[(long long)s2 * 64 + lane];
        float4 u3 = U4[(long long)s3 * 64 + lane];
        a0.x += u0.x; a0.y += u0.y; a0.z += u0.z; a0.w += u0.w;
        a1.x += u1.x; a1.y += u1.y; a1.z += u1.z; a1.w += u1.w;
        a2.x += u2.x; a2.y += u2.y; a2.z += u2.z; a2.w += u2.w;
        a3.x += u3.x; a3.y += u3.y; a3.z += u3.z; a3.w += u3.w;
    }
    for (; j < end; j++) {
        int s0 = bucket[j];
        float4 u = U4[(long long)s0 * 64 + lane];
        a0.x += u.x; a0.y += u.y; a0.z += u.z; a0.w += u.w;
    }
    float4 v = U4[(long long)warp * 64 + 32 + lane];
    int c = lane * 4;
    const float* al = g_alpha[layer];
    const float* be = g_beta[layer];
    float4 o;
    o.x = fmaxf(fmaf((a0.x + a1.x + a2.x + a3.x) * inv + v.x, al[c + 0], be[c + 0]), 0.f);
    o.y = fmaxf(fmaf((a0.y + a1.y + a2.y + a3.y) * inv + v.y, al[c + 1], be[c + 1]), 0.f);
    o.z = fmaxf(fmaf((a0.z + a1.z + a2.z + a3.z) * inv + v.z, al[c + 2], be[c + 2]), 0.f);
    o.w = fmaxf(fmaf((a0.w + a1.w + a2.w + a3.w) * inv + v.w, al[c + 3], be[c + 3]), 0.f);
    // write bf16 hi/lo planes (next GEMM input)
    uint2 hv, lv;
    split4(o, hv, lv);
    *(uint2*)&g_hbf[0][(long long)warp * 128 + c] = hv;
    *(uint2*)&g_hbf[1][(long long)warp * 128 + c] = lv;
}

// final: out[i,:] = mean_nbr u2[s] + v2[i] + b2, g_uv rows are 128 floats here
__global__ void k_aggfinal(const float* __restrict__ b2, float* __restrict__ out) {
    int warp = (blockIdx.x * blockDim.x + threadIdx.x) >> 5;
    int lane = threadIdx.x & 31;
    if (warp >= NN) return;
    int cnt = g_cnt[warp];
    int end = cnt < STRIDE ? cnt : STRIDE;
    float inv = (cnt > 0) ? 1.0f / (float)cnt : 1.0f;
    const int* bucket = &g_colidx[warp * STRIDE];
    const float2* U2 = (const float2*)g_uv;
    float2 a0 = make_float2(0.f, 0.f);
    float2 a1 = make_float2(0.f, 0.f);
    float2 a2 = make_float2(0.f, 0.f);
    float2 a3 = make_float2(0.f, 0.f);
    int j = 0;
    for (; j + 3 < end; j += 4) {
        int s0 = bucket[j], s1 = bucket[j + 1], s2 = bucket[j + 2], s3 = bucket[j + 3];
        float2 u0 = U2[(long long)s0 * 64 + lane];
        float2 u1 = U2[(long long)s1 * 64 + lane];
        float2 u2 = U2[(long long)s2 * 64 + lane];
        float2 u3 = U2[(long long)s3 * 64 + lane];
        a0.x += u0.x; a0.y += u0.y;
        a1.x += u1.x; a1.y += u1.y;
        a2.x += u2.x; a2.y += u2.y;
        a3.x += u3.x; a3.y += u3.y;
    }
    for (; j < end; j++) {
        int s0 = bucket[j];
        float2 u = U2[(long long)s0 * 64 + lane];
        a0.x += u.x; a0.y += u.y;
    }
    float2 v  = U2[(long long)warp * 64 + 32 + lane];
    float2 bb = ((const float2*)b2)[lane];
    float2 o;
    o.x = (a0.x + a1.x + a2.x + a3.x) * inv + v.x + bb.x;
    o.y = (a0.y + a1.y + a2.y + a3.y) * inv + v.y + bb.y;
    ((float2*)out)[(long long)warp * 32 + lane] = o;
}

extern "C" void kernel_launch(void* const* d_in, const int* in_sizes, int n_in,
                              void* d_out, int out_size) {
    const float* x    = (const float*)d_in[0];
    const void*  ei   = d_in[1];
    const float* b_l2 = (const float*)d_in[17];

    long long E = in_sizes[1] / 2;
    if (E > EMAX) E = EMAX;

    cudaFuncSetAttribute(k_gemm7<0>, cudaFuncAttributeMaxDynamicSharedMemorySize, SM_TOT);
    cudaFuncSetAttribute(k_gemm7<1>, cudaFuncAttributeMaxDynamicSharedMemorySize, SM_TOT);

    int mBlocks = (NN + 63) / 64;             // 782
    int aBlocks = (NN * 32 + 255) / 256;      // 6250
    float* uv;
    cudaGetSymbolAddress((void**)&uv, g_uv);

    // fused prolog: zero counters + short width-detect + weight prep
    k_pre<<<320, 256>>>((const long long*)ei, E,
                        (const float*)d_in[3], (const float*)d_in[5], (const float*)d_in[6],
                        (const float*)d_in[7], (const float*)d_in[8],
                        (const float*)d_in[10], (const float*)d_in[12], (const float*)d_in[13],
                        (const float*)d_in[14], (const float*)d_in[15],
                        (const float*)d_in[2], (const float*)d_in[4],
                        (const float*)d_in[9], (const float*)d_in[11],
                        (const float*)d_in[16], (const float*)d_in[18]);
    k_fill<<<512, 256>>>(ei, E);

    // layer 0: uv = x @ [W_l0 | W_r0]; h = relu(bn0(agg(u)+v)) (split to bf16)
    k_gemm7<0><<<dim3(mBlocks, 2), 256, SM_TOT>>>(x, 0, uv, 256);
    k_aggepi<<<aBlocks, 256>>>(0);
    // layer 1
    k_gemm7<1><<<dim3(mBlocks, 2), 256, SM_TOT>>>(nullptr, 32768, uv, 256);
    k_aggepi<<<aBlocks, 256>>>(1);
    // layer 2 (N=128: u2|v2), then final aggregate
    k_gemm7<1><<<dim3(mBlocks, 1), 256, SM_TOT>>>(nullptr, 65536, uv, 128);
    k_aggfinal<<<aBlocks, 256>>>(b_l2, (float*)d_out);
}

// round 14
// speedup vs baseline: 1.1735x; 1.0300x over previous
#include <cuda_runtime.h>
#include <cuda_bf16.h>
#include <cstdint>

#define NN 50000
#define EMAX 600000
#define STRIDE 64

// ---------------- scratch (no allocations allowed) ----------------
__device__ int      g_mode64 = 1;
__device__ int      g_cnt[NN];
__device__ int      g_colidx[NN * STRIDE];
__device__ float    g_uv[NN * 256];   // dual layers: [u(128)|v(128)]; layer2: 128-wide rows
__device__ float    g_alpha[2][128];
__device__ float    g_beta[2][128];
// fragment-ordered split weights:
// per layer: ntile(=N/128) x [kt(8) x 2048], kt-block = [hc(2)][nt(16)][j(2)][lane(32)]
__device__ uint32_t g_Bf[81920];      // L0:[0,32768) L1:[32768,65536) L2:[65536,81920)
// bf16 hi/lo split activations for h (written by aggepi; plane 0 = hi, 1 = lo)
__device__ __nv_bfloat16 g_hbf[2][NN * 128];

// ---------------- index helpers ----------------
__device__ __forceinline__ int load_idx(const void* ei, long long pos) {
    if (g_mode64) return (int)((const long long*)ei)[pos];
    return ((const int*)ei)[pos];
}

// ---------------- split helpers ----------------
__device__ __forceinline__ uint32_t pack2(__nv_bfloat16 a, __nv_bfloat16 b) {
    __nv_bfloat162 t; t.x = a; t.y = b;
    return *(uint32_t*)&t;
}

__device__ __forceinline__ void split4(float4 v, uint2& hv, uint2& lv) {
    __nv_bfloat16 hx = __float2bfloat16(v.x);
    __nv_bfloat16 hy = __float2bfloat16(v.y);
    __nv_bfloat16 hz = __float2bfloat16(v.z);
    __nv_bfloat16 hw = __float2bfloat16(v.w);
    hv.x = pack2(hx, hy); hv.y = pack2(hz, hw);
    lv.x = pack2(__float2bfloat16(v.x - __bfloat162float(hx)),
                 __float2bfloat16(v.y - __bfloat162float(hy)));
    lv.y = pack2(__float2bfloat16(v.z - __bfloat162float(hz)),
                 __float2bfloat16(v.w - __bfloat162float(hw)));
}

__device__ __forceinline__ uint32_t pack_split(float w0, float w1, int hc) {
    __nv_bfloat16 h0 = __float2bfloat16(w0);
    __nv_bfloat16 h1 = __float2bfloat16(w1);
    if (hc) {
        h0 = __float2bfloat16(w0 - __bfloat162float(h0));
        h1 = __float2bfloat16(w1 - __bfloat162float(h1));
    }
    return pack2(h0, h1);
}

// ---------------- fused prolog: zero counters + width-detect + weight prep ----
__global__ void k_pre(const long long* __restrict__ ei, long long nwords,
                      const float* b0, const float* g0, const float* be0,
                      const float* m0, const float* v0,
                      const float* b1, const float* g1, const float* be1,
                      const float* m1, const float* v1,
                      const float* wl0, const float* wr0,
                      const float* wl1, const float* wr1,
                      const float* wl2, const float* wr2) {
    int i = blockIdx.x * blockDim.x + threadIdx.x;
    for (int z = i; z < NN; z += gridDim.x * blockDim.x) g_cnt[z] = 0;
    if (i < 2048 && (long long)i < nwords) {
        long long v = ei[i];
        if (v < 0 || v >= NN) g_mode64 = 0;
    }
    if (i < 128) {
        float s0 = g0[i] * rsqrtf(v0[i] + 1e-5f);
        g_alpha[0][i] = s0;
        g_beta[0][i]  = (b0[i] - m0[i]) * s0 + be0[i];
        float s1 = g1[i] * rsqrtf(v1[i] + 1e-5f);
        g_alpha[1][i] = s1;
        g_beta[1][i]  = (b1[i] - m1[i]) * s1 + be1[i];
    }
    if (i >= 81920) return;
    int layer, idx;
    if (i < 32768)      { layer = 0; idx = i; }
    else if (i < 65536) { layer = 1; idx = i - 32768; }
    else                { layer = 2; idx = i - 65536; }
    int ntile = idx >> 14;
    int sub   = idx & 16383;
    int kt    = sub >> 11;
    int rem   = sub & 2047;
    int hc    = rem >> 10;
    int rem2  = rem & 1023;
    int nt    = rem2 >> 6;
    int j     = (rem2 >> 5) & 1;
    int lane  = rem2 & 31;
    int g = lane >> 2, tg = lane & 3;
    int k = kt * 16 + j * 8 + tg * 2;
    int n = ntile * 128 + nt * 8 + g;
    float w0, w1;
    if (layer == 2) {
        if (n < 64) { w0 = wl2[k * 64 + n];      w1 = wl2[(k + 1) * 64 + n]; }
        else        { w0 = wr2[k * 64 + n - 64]; w1 = wr2[(k + 1) * 64 + n - 64]; }
    } else {
        const float* wl = layer ? wl1 : wl0;
        const float* wr = layer ? wr1 : wr0;
        if (n < 128) { w0 = wl[k * 128 + n];       w1 = wl[(k + 1) * 128 + n]; }
        else         { w0 = wr[k * 128 + n - 128]; w1 = wr[(k + 1) * 128 + n - 128]; }
    }
    g_Bf[i] = pack_split(w0, w1, hc);
}

__device__ __forceinline__ void fill_edges(const void* ei, long long E,
                                           int fidx, int fthreads) {
    for (long long e = fidx; e < E; e += fthreads) {
        int d = load_idx(ei, E + e);
        int s = load_idx(ei, e);
        int p = atomicAdd(&g_cnt[d], 1);
        if (p < STRIDE) g_colidx[d * STRIDE + p] = s;
    }
}

// ---------------- tensor-core GEMM pieces (R10/R13 proven config) ---
__device__ __forceinline__ void mma_bf16(float* c, const uint32_t* a, const uint32_t* b) {
    asm volatile(
        "mma.sync.aligned.m16n8k16.row.col.f32.bf16.bf16.f32 "
        "{%0,%1,%2,%3}, {%4,%5,%6,%7}, {%8,%9}, {%0,%1,%2,%3};\n"
        : "+f"(c[0]), "+f"(c[1]), "+f"(c[2]), "+f"(c[3])
        : "r"(a[0]), "r"(a[1]), "r"(a[2]), "r"(a[3]), "r"(b[0]), "r"(b[1]));
}

__device__ __forceinline__ void ldm_x4(uint32_t* r, const void* p) {
    uint32_t addr = (uint32_t)__cvta_generic_to_shared(p);
    asm volatile("ldmatrix.sync.aligned.m8n8.x4.shared.b16 {%0,%1,%2,%3}, [%4];"
                 : "=r"(r[0]), "=r"(r[1]), "=r"(r[2]), "=r"(r[3]) : "r"(addr));
}

__device__ __forceinline__ void cp_async16(uint32_t d, const void* g) {
    asm volatile("cp.async.cg.shared.global [%0], [%1], 16;" :: "r"(d), "l"(g));
}

// smem: A-hi [8 kb][64 rows][32B, swizzled] 16KB, A-lo 16KB, B 2x16KB = 64KB
#define SMA_HI 0
#define SMA_LO 16384
#define SMB    32768
#define SM_TOT 65536
#define MB64   782            // ceil(NN/64)
#define FILLB  128            // fill blocks per y-plane in hybrid launch

// Core GEMM body: C[64 rows at mb*64, 128 cols at nb*128].
// SELA=0: A = fp32 xf converted inline. SELA=1: A = g_hbf planes via cp.async.
template <int SELA>
__device__ __forceinline__ void gemm_body(
    const float* __restrict__ xf, int bfo, float* __restrict__ C, int ldC,
    int mb, int nb, char* sm)
{
    uint32_t smb = (uint32_t)__cvta_generic_to_shared(sm);
    uint32_t* sB32 = (uint32_t*)(sm + SMB);

    int tid = threadIdx.x, lane = tid & 31, wid = tid >> 5;
    int warpM = wid & 3, warpN = wid >> 2;      // 4 x 2 warps, tile 16x64 each
    int m0 = mb * 64;
    const uint32_t* Bf = g_Bf + bfo + nb * 16384;

    float acc[8][4];
    #pragma unroll
    for (int b = 0; b < 8; b++)
        #pragma unroll
        for (int c = 0; c < 4; c++) acc[b][c] = 0.f;

    // ---- stage A (64 rows, full K, hi/lo planes, XOR-swizzled) ----
    if (SELA == 0) {
        #pragma unroll
        for (int q = 0; q < 8; q++) {
            int f = tid + q * 256;               // 0..2047 float4s
            int row = f >> 5, c4 = f & 31;       // row 0..63, k4 0..31
            int gr = m0 + row;
            if (gr >= NN) gr = NN - 1;
            float4 v = ((const float4*)xf)[(long long)gr * 32 + c4];
            uint2 hv, lv;
            split4(v, hv, lv);
            int kb  = c4 >> 2;                   // 16-k block
            int c16 = (c4 >> 1) & 1;             // 16B chunk within kb
            int ph  = c16 ^ ((row >> 2) & 1);
            uint32_t doff = (uint32_t)(kb * 2048 + row * 32 + ph * 16 + (c4 & 1) * 8);
            *(uint2*)(sm + SMA_HI + doff) = hv;
            *(uint2*)(sm + SMA_LO + doff) = lv;
        }
    } else {
        #pragma unroll
        for (int i = 0; i < 4; i++) {
            int idx = tid + i * 256;             // 0..1023 16B-chunks
            int row = idx >> 4, c = idx & 15;
            int kb = c >> 1, ph = (c & 1) ^ ((row >> 2) & 1);
            uint32_t doff = (uint32_t)(kb * 2048 + row * 32 + ph * 16);
            int gr = m0 + row;
            if (gr >= NN) gr = NN - 1;
            long long goff = (long long)gr * 128 + c * 8;
            cp_async16(smb + SMA_HI + doff, g_hbf[0] + goff);
            cp_async16(smb + SMA_LO + doff, g_hbf[1] + goff);
        }
    }
    // B chunk 0 into buf 0
    {
        const uint4* src = (const uint4*)(Bf);
        #pragma unroll
        for (int r = 0; r < 4; r++)
            cp_async16(smb + SMB + tid * 16 + r * 4096, src + tid + r * 256);
    }
    asm volatile("cp.async.commit_group;");          // G0 = (A?) + B0
    {
        const uint4* src = (const uint4*)(Bf + 4096);
        #pragma unroll
        for (int r = 0; r < 4; r++)
            cp_async16(smb + SMB + 16384 + tid * 16 + r * 4096, src + tid + r * 256);
    }
    asm volatile("cp.async.commit_group;");          // G1 = B1

    for (int it = 0; it < 4; it++) {
        if (it < 3) asm volatile("cp.async.wait_group 1;");
        else        asm volatile("cp.async.wait_group 0;");
        __syncthreads();

        int buf = it & 1;
        #pragma unroll
        for (int kt2 = 0; kt2 < 2; kt2++) {
            int kt = it * 2 + kt2;
            uint32_t ah[4], al[4];
            {
                int r = warpM * 16 + (lane & 15);
                int ch = lane >> 4;
                uint32_t off = (uint32_t)(kt * 2048 + r * 32 + ((ch ^ ((r >> 2) & 1)) << 4));
                ldm_x4(ah, sm + SMA_HI + off);
                ldm_x4(al, sm + SMA_LO + off);
            }
            uint32_t bbase = (uint32_t)(buf * 4096 + kt2 * 2048);
            #pragma unroll
            for (int ntl = 0; ntl < 8; ntl++) {
                int nt = warpN * 8 + ntl;
                uint32_t bh[2], bl[2];
                bh[0] = sB32[bbase + nt * 64 + lane];
                bh[1] = sB32[bbase + nt * 64 + 32 + lane];
                bl[0] = sB32[bbase + 1024 + nt * 64 + lane];
                bl[1] = sB32[bbase + 1024 + nt * 64 + 32 + lane];
                mma_bf16(acc[ntl], ah, bh);
                mma_bf16(acc[ntl], ah, bl);
                mma_bf16(acc[ntl], al, bh);
            }
        }
        if (it < 2) {
            __syncthreads();                          // all warps done with buf
            const uint4* src = (const uint4*)(Bf + (it + 2) * 4096);
            uint32_t dst = smb + SMB + (uint32_t)(buf * 16384);
            #pragma unroll
            for (int r = 0; r < 4; r++)
                cp_async16(dst + tid * 16 + r * 4096, src + tid + r * 256);
            asm volatile("cp.async.commit_group;");
        }
    }

    // ---- epilogue: raw fp32 store of fragments ----
    int g = lane >> 2, tg = lane & 3;
    #pragma unroll
    for (int ntl = 0; ntl < 8; ntl++) {
        int c = nb * 128 + warpN * 64 + ntl * 8 + tg * 2;
        int r0 = m0 + warpM * 16 + g;
        int r1 = r0 + 8;
        float2 v0 = make_float2(acc[ntl][0], acc[ntl][1]);
        float2 v1 = make_float2(acc[ntl][2], acc[ntl][3]);
        if (r0 < NN) *(float2*)&C[(long long)r0 * ldC + c] = v0;
        if (r1 < NN) *(float2*)&C[(long long)r1 * ldC + c] = v1;
    }
}

// Hybrid layer-0 kernel: GEMM blocks + graph-fill blocks in one grid.
// grid = (MB64 + FILLB, 2). Blocks with blockIdx.x >= MB64 do edge fill.
__global__ __launch_bounds__(256, 3) void k_gemm0f(
    const float* __restrict__ xf, float* __restrict__ C,
    const void* __restrict__ ei, long long E)
{
    extern __shared__ char sm[];
    if (blockIdx.x < MB64) {
        gemm_body<0>(xf, 0, C, 256, blockIdx.x, blockIdx.y, sm);
    } else {
        int fb = (blockIdx.x - MB64) + blockIdx.y * FILLB;   // 0..255
        fill_edges(ei, E, fb * 256 + threadIdx.x, 2 * FILLB * 256);
    }
}

// Plain GEMM kernel for layers 1/2 (A from g_hbf).
__global__ __launch_bounds__(256, 3) void k_gemm7(
    int bfo, float* __restrict__ C, int ldC)
{
    extern __shared__ char sm[];
    gemm_body<1>(nullptr, bfo, C, ldC, blockIdx.x, blockIdx.y, sm);
}

// ---------------- fused aggregate + BN/ReLU + bf16-split epilogue ----
__global__ void k_aggepi(int layer) {
    int warp = (blockIdx.x * blockDim.x + threadIdx.x) >> 5;
    int lane = threadIdx.x & 31;
    if (warp >= NN) return;
    int cnt = g_cnt[warp];
    int end = cnt < STRIDE ? cnt : STRIDE;
    float inv = (cnt > 0) ? 1.0f / (float)cnt : 1.0f;
    const int* bucket = &g_colidx[warp * STRIDE];
    const float4* U4 = (const float4*)g_uv;
    float4 a0 = make_float4(0.f, 0.f, 0.f, 0.f);
    float4 a1 = make_float4(0.f, 0.f, 0.f, 0.f);
    float4 a2 = make_float4(0.f, 0.f, 0.f, 0.f);
    float4 a3 = make_float4(0.f, 0.f, 0.f, 0.f);
    int j = 0;
    for (; j + 3 < end; j += 4) {
        int s0 = bucket[j], s1 = bucket[j + 1], s2 = bucket[j + 2], s3 = bucket[j + 3];
        float4 u0 = U4[(long long)s0 * 64 + lane];
        float4 u1 = U4[(long long)s1 * 64 + lane];
        float4 u2 = U4[(long long)s2 * 64 + lane];
        float4 u3 = U4[(long long)s3 * 64 + lane];
        a0.x += u0.x; a0.y += u0.y; a0.z += u0.z; a0.w += u0.w;
        a1.x += u1.x; a1.y += u1.y; a1.z += u1.z; a1.w += u1.w;
        a2.x += u2.x; a2.y += u2.y; a2.z += u2.z; a2.w += u2.w;
        a3.x += u3.x; a3.y += u3.y; a3.z += u3.z; a3.w += u3.w;
    }
    for (; j < end; j++) {
        int s0 = bucket[j];
        float4 u = U4[(long long)s0 * 64 + lane];
        a0.x += u.x; a0.y += u.y; a0.z += u.z; a0.w += u.w;
    }
    float4 v = U4[(long long)warp * 64 + 32 + lane];
    int c = lane * 4;
    const float* al = g_alpha[layer];
    const float* be = g_beta[layer];
    float4 o;
    o.x = fmaxf(fmaf((a0.x + a1.x + a2.x + a3.x) * inv + v.x, al[c + 0], be[c + 0]), 0.f);
    o.y = fmaxf(fmaf((a0.y + a1.y + a2.y + a3.y) * inv + v.y, al[c + 1], be[c + 1]), 0.f);
    o.z = fmaxf(fmaf((a0.z + a1.z + a2.z + a3.z) * inv + v.z, al[c + 2], be[c + 2]), 0.f);
    o.w = fmaxf(fmaf((a0.w + a1.w + a2.w + a3.w) * inv + v.w, al[c + 3], be[c + 3]), 0.f);
    // write bf16 hi/lo planes (next GEMM input)
    uint2 hv, lv;
    split4(o, hv, lv);
    *(uint2*)&g_hbf[0][(long long)warp * 128 + c] = hv;
    *(uint2*)&g_hbf[1][(long long)warp * 128 + c] = lv;
}

// final: out[i,:] = mean_nbr u2[s] + v2[i] + b2, g_uv rows are 128 floats here
__global__ void k_aggfinal(const float* __restrict__ b2, float* __restrict__ out) {
    int warp = (blockIdx.x * blockDim.x + threadIdx.x) >> 5;
    int lane = threadIdx.x & 31;
    if (warp >= NN) return;
    int cnt = g_cnt[warp];
    int end = cnt < STRIDE ? cnt : STRIDE;
    float inv = (cnt > 0) ? 1.0f / (float)cnt : 1.0f;
    const int* bucket = &g_colidx[warp * STRIDE];
    const float2* U2 = (const float2*)g_uv;
    float2 a0 = make_float2(0.f, 0.f);
    float2 a1 = make_float2(0.f, 0.f);
    float2 a2 = make_float2(0.f, 0.f);
    float2 a3 = make_float2(0.f, 0.f);
    int j = 0;
    for (; j + 3 < end; j += 4) {
        int s0 = bucket[j], s1 = bucket[j + 1], s2 = bucket[j + 2], s3 = bucket[j + 3];
        float2 u0 = U2[(long long)s0 * 64 + lane];
        float2 u1 = U2[(long long)s1 * 64 + lane];
        float2 u2 = U2[(long long)s2 * 64 + lane];
        float2 u3 = U2[(long long)s3 * 64 + lane];
        a0.x += u0.x; a0.y += u0.y;
        a1.x += u1.x; a1.y += u1.y;
        a2.x += u2.x; a2.y += u2.y;
        a3.x += u3.x; a3.y += u3.y;
    }
    for (; j < end; j++) {
        int s0 = bucket[j];
        float2 u = U2[(long long)s0 * 64 + lane];
        a0.x += u.x; a0.y += u.y;
    }
    float2 v  = U2[(long long)warp * 64 + 32 + lane];
    float2 bb = ((const float2*)b2)[lane];
    float2 o;
    o.x = (a0.x + a1.x + a2.x + a3.x) * inv + v.x + bb.x;
    o.y = (a0.y + a1.y + a2.y + a3.y) * inv + v.y + bb.y;
    ((float2*)out)[(long long)warp * 32 + lane] = o;
}

extern "C" void kernel_launch(void* const* d_in, const int* in_sizes, int n_in,
                              void* d_out, int out_size) {
    const float* x    = (const float*)d_in[0];
    const void*  ei   = d_in[1];
    const float* b_l2 = (const float*)d_in[17];

    long long E = in_sizes[1] / 2;
    if (E > EMAX) E = EMAX;

    cudaFuncSetAttribute(k_gemm0f, cudaFuncAttributeMaxDynamicSharedMemorySize, SM_TOT);
    cudaFuncSetAttribute(k_gemm7, cudaFuncAttributeMaxDynamicSharedMemorySize, SM_TOT);

    int aBlocks = (NN * 32 + 255) / 256;      // 6250
    float* uv;
    cudaGetSymbolAddress((void**)&uv, g_uv);

    // fused prolog: zero counters + short width-detect + weight prep
    k_pre<<<320, 256>>>((const long long*)ei, E,
                        (const float*)d_in[3], (const float*)d_in[5], (const float*)d_in[6],
                        (const float*)d_in[7], (const float*)d_in[8],
                        (const float*)d_in[10], (const float*)d_in[12], (const float*)d_in[13],
                        (const float*)d_in[14], (const float*)d_in[15],
                        (const float*)d_in[2], (const float*)d_in[4],
                        (const float*)d_in[9], (const float*)d_in[11],
                        (const float*)d_in[16], (const float*)d_in[18]);

    // layer 0 (hybrid): uv = x @ [W_l0 | W_r0]  ||  graph fill
    k_gemm0f<<<dim3(MB64 + FILLB, 2), 256, SM_TOT>>>(x, uv, ei, E);
    k_aggepi<<<aBlocks, 256>>>(0);
    // layer 1
    k_gemm7<<<dim3(MB64, 2), 256, SM_TOT>>>(32768, uv, 256);
    k_aggepi<<<aBlocks, 256>>>(1);
    // layer 2 (N=128: u2|v2), then final aggregate
    k_gemm7<<<dim3(MB64, 1), 256, SM_TOT>>>(65536, uv, 128);
    k_aggfinal<<<aBlocks, 256>>>(b_l2, (float*)d_out);
}